// round 1
// baseline (speedup 1.0000x reference)
#include <cuda_runtime.h>
#include <math.h>

#define NN 100000
#define EE 640000
#define DD 128
#define HH 256
#define LL 3
#define QDIM 768

// ---------------- scratch (device globals; no allocations allowed) ----------
__device__ float g_nodeA[(size_t)NN * DD];
__device__ float g_nodeB[(size_t)NN * DD];
__device__ float g_edgeA[(size_t)EE * DD];
__device__ float g_edgeB[(size_t)EE * DD];
__device__ float g_agg[(size_t)NN * DD];
__device__ float g_q[DD];
__device__ float g_qbias[HH];

// ---------------- small kernels ---------------------------------------------
__global__ void zero_kernel(float4* p, int n4) {
    int i = blockIdx.x * blockDim.x + threadIdx.x;
    if (i < n4) p[i] = make_float4(0.f, 0.f, 0.f, 0.f);
}

// q = question[768] @ qW[768,128] + qb
__global__ void q_proj_kernel(const float* __restrict__ qe,
                              const float* __restrict__ qW,
                              const float* __restrict__ qb,
                              float* __restrict__ qout) {
    int d = threadIdx.x;  // 128 threads
    float s = qb[d];
    for (int k = 0; k < QDIM; k++) s += qe[k] * qW[(size_t)k * DD + d];
    qout[d] = s;
}

// qbias[h] = eb1[h] + sum_k q[k] * eW1l[(384+k)*256 + h]
__global__ void qbias_kernel(const float* __restrict__ q,
                             const float* __restrict__ eW1l,
                             const float* __restrict__ eb1l,
                             float* __restrict__ qbias) {
    int h = threadIdx.x;  // 256 threads
    float s = eb1l[h];
    for (int k = 0; k < DD; k++) s += q[k] * eW1l[(size_t)(384 + k) * HH + h];
    qbias[h] = s;
}

// sigmoid(h_row . w + b) per row; one warp per row
__global__ void score_kernel(const float* __restrict__ h,
                             const float* __restrict__ w,
                             const float* __restrict__ bptr,
                             float* __restrict__ out, int count) {
    int gwarp = (blockIdx.x * blockDim.x + threadIdx.x) >> 5;
    int lane = threadIdx.x & 31;
    if (gwarp >= count) return;
    float4 a = ((const float4*)(h + (size_t)gwarp * DD))[lane];
    float4 wv = ((const float4*)w)[lane];
    float s = a.x * wv.x + a.y * wv.y + a.z * wv.z + a.w * wv.w;
    #pragma unroll
    for (int o = 16; o; o >>= 1) s += __shfl_xor_sync(0xffffffffu, s, o);
    if (lane == 0) {
        float x = s + bptr[0];
        out[gwarp] = 1.f / (1.f + expf(-x));
    }
}

// ---------------- fused edge MLP --------------------------------------------
// 32 edges per block. GEMM1: [32,384]@[384,256] (+qbias, relu) -> smem hs
// GEMM2: [32,256]@[256,128] (+b2) -> edge_out, atomic scatter to agg[src],agg[dst]
__global__ __launch_bounds__(256) void edge_mlp_kernel(
    const float* __restrict__ node_in, const float* __restrict__ edge_in,
    const int* __restrict__ src, const int* __restrict__ dst,
    const float* __restrict__ W1, const float* __restrict__ W2,
    const float* __restrict__ b2, const float* __restrict__ qbias,
    float* __restrict__ edge_out, float* __restrict__ agg) {
    __shared__ union {
        struct { float As[16][32]; float Bs[16][256]; } g1;     // 18.0 KB
        struct { float hs[32][256]; float Ws[16][128]; } g2;    // 40.0 KB
    } sm;
    __shared__ float qb_s[HH];
    __shared__ float b2_s[DD];
    __shared__ int s_src[32], s_dst[32];

    int tid = threadIdx.x;
    int e0 = blockIdx.x * 32;
    if (tid < 32) { s_src[tid] = src[e0 + tid]; s_dst[tid] = dst[e0 + tid]; }
    qb_s[tid] = qbias[tid];
    if (tid < DD) b2_s[tid] = b2[tid];
    __syncthreads();

    int tx = tid & 31, ty = tid >> 5;
    float acc[4][8];
    #pragma unroll
    for (int i = 0; i < 4; i++)
        #pragma unroll
        for (int j = 0; j < 8; j++) acc[i][j] = 0.f;

    for (int kt = 0; kt < 24; kt++) {
        int kbase = kt * 16;
        if (tid < 128) {
            int m = tid >> 2, q4 = tid & 3;
            int k = kbase + q4 * 4;
            const float* p;
            if (k < 128)      p = node_in + (size_t)s_src[m] * DD + k;
            else if (k < 256) p = node_in + (size_t)s_dst[m] * DD + (k - 128);
            else              p = edge_in + (size_t)(e0 + m) * DD + (k - 256);
            float4 v = *(const float4*)p;
            sm.g1.As[q4 * 4 + 0][m] = v.x;
            sm.g1.As[q4 * 4 + 1][m] = v.y;
            sm.g1.As[q4 * 4 + 2][m] = v.z;
            sm.g1.As[q4 * 4 + 3][m] = v.w;
        }
        const float4* Bg = (const float4*)(W1 + (size_t)kbase * HH);
        #pragma unroll
        for (int i = 0; i < 4; i++) {
            int f = tid + i * 256;
            int kk = f >> 6, cv = f & 63;
            *(float4*)&sm.g1.Bs[kk][cv * 4] = Bg[kk * 64 + cv];
        }
        __syncthreads();
        #pragma unroll
        for (int kk = 0; kk < 16; kk++) {
            float a0 = sm.g1.As[kk][ty * 4 + 0];
            float a1 = sm.g1.As[kk][ty * 4 + 1];
            float a2 = sm.g1.As[kk][ty * 4 + 2];
            float a3 = sm.g1.As[kk][ty * 4 + 3];
            float4 bb0 = *(const float4*)&sm.g1.Bs[kk][tx * 8];
            float4 bb1 = *(const float4*)&sm.g1.Bs[kk][tx * 8 + 4];
            float bv[8] = {bb0.x, bb0.y, bb0.z, bb0.w, bb1.x, bb1.y, bb1.z, bb1.w};
            #pragma unroll
            for (int j = 0; j < 8; j++) {
                acc[0][j] += a0 * bv[j];
                acc[1][j] += a1 * bv[j];
                acc[2][j] += a2 * bv[j];
                acc[3][j] += a3 * bv[j];
            }
        }
        __syncthreads();
    }

    // bias + relu -> hs (union region: everyone past final sync above)
    #pragma unroll
    for (int i = 0; i < 4; i++)
        #pragma unroll
        for (int j = 0; j < 8; j++) {
            float v = acc[i][j] + qb_s[tx * 8 + j];
            sm.g2.hs[ty * 4 + i][tx * 8 + j] = v > 0.f ? v : 0.f;
        }
    __syncthreads();

    float acc2[4][4];
    #pragma unroll
    for (int i = 0; i < 4; i++)
        #pragma unroll
        for (int j = 0; j < 4; j++) acc2[i][j] = 0.f;

    for (int kb = 0; kb < HH; kb += 16) {
        #pragma unroll
        for (int i = 0; i < 2; i++) {
            int f = tid + i * 256;
            int kk = f >> 5, cv = f & 31;
            *(float4*)&sm.g2.Ws[kk][cv * 4] =
                *(const float4*)(W2 + (size_t)(kb + kk) * DD + cv * 4);
        }
        __syncthreads();
        #pragma unroll
        for (int kk = 0; kk < 16; kk++) {
            float4 w = *(const float4*)&sm.g2.Ws[kk][tx * 4];
            #pragma unroll
            for (int i = 0; i < 4; i++) {
                float a = sm.g2.hs[ty * 4 + i][kb + kk];
                acc2[i][0] += a * w.x;
                acc2[i][1] += a * w.y;
                acc2[i][2] += a * w.z;
                acc2[i][3] += a * w.w;
            }
        }
        __syncthreads();
    }

    #pragma unroll
    for (int i = 0; i < 4; i++) {
        int row = ty * 4 + i;
        int e = e0 + row;
        int s = s_src[row], d = s_dst[row];
        #pragma unroll
        for (int j = 0; j < 4; j++) {
            int col = tx * 4 + j;
            float v = acc2[i][j] + b2_s[col];
            edge_out[(size_t)e * DD + col] = v;
            atomicAdd(&agg[(size_t)s * DD + col], v);
            atomicAdd(&agg[(size_t)d * DD + col], v);
        }
    }
}

// ---------------- fused node MLP --------------------------------------------
// 32 nodes/block. GEMM1: [32,256]@[256,256] (+b1,relu) -> GEMM2 [32,256]@[256,128]
__global__ __launch_bounds__(256) void node_mlp_kernel(
    const float* __restrict__ node_in, const float* __restrict__ agg,
    const float* __restrict__ W1, const float* __restrict__ b1,
    const float* __restrict__ W2, const float* __restrict__ b2,
    float* __restrict__ node_out) {
    __shared__ union {
        struct { float As[16][32]; float Bs[16][256]; } g1;
        struct { float hs[32][256]; float Ws[16][128]; } g2;
    } sm;
    __shared__ float b1_s[HH];
    __shared__ float b2_s[DD];

    int tid = threadIdx.x;
    int n0 = blockIdx.x * 32;
    b1_s[tid] = b1[tid];
    if (tid < DD) b2_s[tid] = b2[tid];
    __syncthreads();

    int tx = tid & 31, ty = tid >> 5;
    float acc[4][8];
    #pragma unroll
    for (int i = 0; i < 4; i++)
        #pragma unroll
        for (int j = 0; j < 8; j++) acc[i][j] = 0.f;

    for (int kt = 0; kt < 16; kt++) {
        int kbase = kt * 16;
        if (tid < 128) {
            int m = tid >> 2, q4 = tid & 3;
            int k = kbase + q4 * 4;
            const float* p;
            if (k < 128) p = node_in + (size_t)(n0 + m) * DD + k;
            else         p = agg + (size_t)(n0 + m) * DD + (k - 128);
            float4 v = *(const float4*)p;
            sm.g1.As[q4 * 4 + 0][m] = v.x;
            sm.g1.As[q4 * 4 + 1][m] = v.y;
            sm.g1.As[q4 * 4 + 2][m] = v.z;
            sm.g1.As[q4 * 4 + 3][m] = v.w;
        }
        const float4* Bg = (const float4*)(W1 + (size_t)kbase * HH);
        #pragma unroll
        for (int i = 0; i < 4; i++) {
            int f = tid + i * 256;
            int kk = f >> 6, cv = f & 63;
            *(float4*)&sm.g1.Bs[kk][cv * 4] = Bg[kk * 64 + cv];
        }
        __syncthreads();
        #pragma unroll
        for (int kk = 0; kk < 16; kk++) {
            float a0 = sm.g1.As[kk][ty * 4 + 0];
            float a1 = sm.g1.As[kk][ty * 4 + 1];
            float a2 = sm.g1.As[kk][ty * 4 + 2];
            float a3 = sm.g1.As[kk][ty * 4 + 3];
            float4 bb0 = *(const float4*)&sm.g1.Bs[kk][tx * 8];
            float4 bb1 = *(const float4*)&sm.g1.Bs[kk][tx * 8 + 4];
            float bv[8] = {bb0.x, bb0.y, bb0.z, bb0.w, bb1.x, bb1.y, bb1.z, bb1.w};
            #pragma unroll
            for (int j = 0; j < 8; j++) {
                acc[0][j] += a0 * bv[j];
                acc[1][j] += a1 * bv[j];
                acc[2][j] += a2 * bv[j];
                acc[3][j] += a3 * bv[j];
            }
        }
        __syncthreads();
    }

    #pragma unroll
    for (int i = 0; i < 4; i++)
        #pragma unroll
        for (int j = 0; j < 8; j++) {
            float v = acc[i][j] + b1_s[tx * 8 + j];
            sm.g2.hs[ty * 4 + i][tx * 8 + j] = v > 0.f ? v : 0.f;
        }
    __syncthreads();

    float acc2[4][4];
    #pragma unroll
    for (int i = 0; i < 4; i++)
        #pragma unroll
        for (int j = 0; j < 4; j++) acc2[i][j] = 0.f;

    for (int kb = 0; kb < HH; kb += 16) {
        #pragma unroll
        for (int i = 0; i < 2; i++) {
            int f = tid + i * 256;
            int kk = f >> 5, cv = f & 31;
            *(float4*)&sm.g2.Ws[kk][cv * 4] =
                *(const float4*)(W2 + (size_t)(kb + kk) * DD + cv * 4);
        }
        __syncthreads();
        #pragma unroll
        for (int kk = 0; kk < 16; kk++) {
            float4 w = *(const float4*)&sm.g2.Ws[kk][tx * 4];
            #pragma unroll
            for (int i = 0; i < 4; i++) {
                float a = sm.g2.hs[ty * 4 + i][kb + kk];
                acc2[i][0] += a * w.x;
                acc2[i][1] += a * w.y;
                acc2[i][2] += a * w.z;
                acc2[i][3] += a * w.w;
            }
        }
        __syncthreads();
    }

    #pragma unroll
    for (int i = 0; i < 4; i++) {
        int row = n0 + ty * 4 + i;
        #pragma unroll
        for (int j = 0; j < 4; j++) {
            int col = tx * 4 + j;
            node_out[(size_t)row * DD + col] = acc2[i][j] + b2_s[col];
        }
    }
}

// ---------------- launch ----------------------------------------------------
extern "C" void kernel_launch(void* const* d_in, const int* in_sizes, int n_in,
                              void* d_out, int out_size) {
    const float* node_emb = (const float*)d_in[0];
    const float* rel_emb  = (const float*)d_in[1];
    const float* q_emb    = (const float*)d_in[2];
    const int*   eidx     = (const int*)d_in[3];
    // d_in[4] = edge_type, unused (matches reference)
    const float* qW  = (const float*)d_in[5];
    const float* qb  = (const float*)d_in[6];
    const float* eW1 = (const float*)d_in[7];
    const float* eb1 = (const float*)d_in[8];
    const float* eW2 = (const float*)d_in[9];
    const float* eb2 = (const float*)d_in[10];
    const float* nW1 = (const float*)d_in[11];
    const float* nb1 = (const float*)d_in[12];
    const float* nW2 = (const float*)d_in[13];
    const float* nb2 = (const float*)d_in[14];
    const float* esW = (const float*)d_in[15];
    const float* esb = (const float*)d_in[16];
    const float* nsW = (const float*)d_in[17];
    const float* nsb = (const float*)d_in[18];
    const int* src = eidx;
    const int* dst = eidx + EE;

    float *nodeA, *nodeB, *edgeA, *edgeB, *agg, *qv, *qbias;
    cudaGetSymbolAddress((void**)&nodeA, g_nodeA);
    cudaGetSymbolAddress((void**)&nodeB, g_nodeB);
    cudaGetSymbolAddress((void**)&edgeA, g_edgeA);
    cudaGetSymbolAddress((void**)&edgeB, g_edgeB);
    cudaGetSymbolAddress((void**)&agg, g_agg);
    cudaGetSymbolAddress((void**)&qv, g_q);
    cudaGetSymbolAddress((void**)&qbias, g_qbias);

    q_proj_kernel<<<1, 128>>>(q_emb, qW, qb, qv);

    const float* nin = node_emb;
    const float* ein = rel_emb;
    float* nout = nodeA; float* nalt = nodeB;
    float* eout = edgeA; float* ealt = edgeB;

    for (int l = 0; l < LL; l++) {
        int n4 = NN * DD / 4;
        zero_kernel<<<(n4 + 255) / 256, 256>>>((float4*)agg, n4);
        qbias_kernel<<<1, 256>>>(qv, eW1 + (size_t)l * 512 * HH,
                                 eb1 + (size_t)l * HH, qbias);
        edge_mlp_kernel<<<EE / 32, 256>>>(nin, ein, src, dst,
                                          eW1 + (size_t)l * 512 * HH,
                                          eW2 + (size_t)l * HH * DD,
                                          eb2 + (size_t)l * DD, qbias, eout, agg);
        node_mlp_kernel<<<NN / 32, 256>>>(nin, agg,
                                          nW1 + (size_t)l * 2 * DD * HH,
                                          nb1 + (size_t)l * HH,
                                          nW2 + (size_t)l * HH * DD,
                                          nb2 + (size_t)l * DD, nout);
        nin = nout; ein = eout;
        float* t;
        t = nout; nout = nalt; nalt = t;
        t = eout; eout = ealt; ealt = t;
    }

    float* outp = (float*)d_out;
    score_kernel<<<(NN + 7) / 8, 256>>>(nin, nsW, nsb, outp, NN);
    score_kernel<<<(EE + 7) / 8, 256>>>(ein, esW, esb, outp + NN, EE);
}

// round 5
// speedup vs baseline: 5.0762x; 5.0762x over previous
#include <cuda_runtime.h>
#include <cstdint>
#include <math.h>

#define NN 100000
#define EE 640000
#define DDIM 128
#define HHID 256
#define LLAY 3
#define QDIM 768

// ---------------- device scratch (no allocations allowed) -------------------
__device__ float g_nodeA[(size_t)NN * DDIM];
__device__ float g_nodeB[(size_t)NN * DDIM];
__device__ float g_edgeA[(size_t)EE * DDIM];
__device__ float g_edgeB[(size_t)EE * DDIM];
__device__ float g_agg[(size_t)NN * DDIM];
__device__ float g_q[DDIM];
__device__ float g_qbias[HHID];
__device__ float g_eW1T[256 * 384];   // [N=256, K=384] tf32
__device__ float g_eW2T[128 * 256];   // [N=128, K=256] tf32
__device__ float g_nW1T[256 * 256];   // [N=256, K=256] tf32
__device__ float g_nW2T[128 * 256];   // [N=128, K=256] tf32

// ---------------- helpers ----------------------------------------------------
__device__ __forceinline__ uint32_t f2tf32(float f) {
    uint32_t u;
    asm("cvt.rna.tf32.f32 %0, %1;" : "=r"(u) : "f"(f));
    return u;
}
__device__ __forceinline__ float tf32f(float f) { return __uint_as_float(f2tf32(f)); }

__device__ __forceinline__ void mma8(float* d, const uint32_t* a, uint32_t b0, uint32_t b1) {
    asm volatile(
        "mma.sync.aligned.m16n8k8.row.col.f32.tf32.tf32.f32 "
        "{%0,%1,%2,%3}, {%4,%5,%6,%7}, {%8,%9}, {%0,%1,%2,%3};"
        : "+f"(d[0]), "+f"(d[1]), "+f"(d[2]), "+f"(d[3])
        : "r"(a[0]), "r"(a[1]), "r"(a[2]), "r"(a[3]), "r"(b0), "r"(b1));
}
__device__ __forceinline__ void red2(float* p, float x, float y) {
    asm volatile("red.global.add.v2.f32 [%0], {%1, %2};"
                 :: "l"(p), "f"(x), "f"(y) : "memory");
}

// smem layout in float words
enum {
    HS_STRIDE = 264,
    HS_OFF = 0,                       // 128 x 264           = 33792
    AS_OFF = 33792, AS_STRIDE = 36,   // 128 x 36            = 4608
    BS_OFF = 38400, BS_STRIDE = 36,   // 256 x 36            = 9216
    QB_OFF = 47616,                   // 256
    B2_OFF = 47872,                   // 128
    SS_OFF = 48000,                   // 128 (int)
    SD_OFF = 48128,                   // 128 (int)
    SM_WORDS = 48256
};
#define SMEM_BYTES (SM_WORDS * 4)

// ---------------- small kernels ---------------------------------------------
__global__ void zero_kernel(float4* p, int n4) {
    int i = blockIdx.x * blockDim.x + threadIdx.x;
    if (i < n4) p[i] = make_float4(0.f, 0.f, 0.f, 0.f);
}
__global__ void q_proj_kernel(const float* __restrict__ qe, const float* __restrict__ qW,
                              const float* __restrict__ qb, float* __restrict__ qout) {
    int d = threadIdx.x;
    float s = qb[d];
    for (int k = 0; k < QDIM; k++) s += qe[k] * qW[(size_t)k * DDIM + d];
    qout[d] = s;
}
__global__ void qbias_kernel(const float* __restrict__ q, const float* __restrict__ eW1l,
                             const float* __restrict__ eb1l, float* __restrict__ qbias) {
    int h = threadIdx.x;
    float s = eb1l[h];
    for (int k = 0; k < DDIM; k++) s += q[k] * eW1l[(size_t)(384 + k) * HHID + h];
    qbias[h] = s;
}
// out[n*K + k] = tf32(in[k*N + n])
__global__ void transpose_tf32_kernel(const float* __restrict__ in, float* __restrict__ out,
                                      int K, int N) {
    int i = blockIdx.x * blockDim.x + threadIdx.x;
    if (i >= N * K) return;
    int n = i / K, k = i - n * K;
    out[i] = tf32f(in[(size_t)k * N + n]);
}
__global__ void score_kernel(const float* __restrict__ h, const float* __restrict__ w,
                             const float* __restrict__ bptr, float* __restrict__ out, int count) {
    int gwarp = (blockIdx.x * blockDim.x + threadIdx.x) >> 5;
    int lane = threadIdx.x & 31;
    if (gwarp >= count) return;
    float4 a = ((const float4*)(h + (size_t)gwarp * DDIM))[lane];
    float4 wv = ((const float4*)w)[lane];
    float s = a.x * wv.x + a.y * wv.y + a.z * wv.z + a.w * wv.w;
    #pragma unroll
    for (int o = 16; o; o >>= 1) s += __shfl_xor_sync(0xffffffffu, s, o);
    if (lane == 0) out[gwarp] = 1.f / (1.f + expf(-(s + bptr[0])));
}

// ---------------- shared GEMM pieces -----------------------------------------
// GEMM1 (N=256): warp grid 4(M) x 4(N), warp tile 32x64, accum d1[2][8][4]
// GEMM2 (N=128): warp grid 4(M) x 4(N), warp tile 32x32, accum d2[2][4][4]

__device__ __forceinline__ void gemm1_chunk_mma(const float* As, const float* Bs,
                                                int mw, int nw, int g, int t,
                                                float d1[2][8][4]) {
    #pragma unroll
    for (int ks = 0; ks < 4; ks++) {
        int k = ks * 8;
        uint32_t a[2][4];
        #pragma unroll
        for (int mt = 0; mt < 2; mt++) {
            int r = mw * 32 + mt * 16;
            a[mt][0] = __float_as_uint(As[(r + g) * AS_STRIDE + k + t]);
            a[mt][1] = __float_as_uint(As[(r + g + 8) * AS_STRIDE + k + t]);
            a[mt][2] = __float_as_uint(As[(r + g) * AS_STRIDE + k + t + 4]);
            a[mt][3] = __float_as_uint(As[(r + g + 8) * AS_STRIDE + k + t + 4]);
        }
        #pragma unroll
        for (int nt = 0; nt < 8; nt++) {
            int n = nw * 64 + nt * 8;
            uint32_t b0 = __float_as_uint(Bs[(n + g) * BS_STRIDE + k + t]);
            uint32_t b1 = __float_as_uint(Bs[(n + g) * BS_STRIDE + k + t + 4]);
            mma8(d1[0][nt], a[0], b0, b1);
            mma8(d1[1][nt], a[1], b0, b1);
        }
    }
}

__device__ __forceinline__ void write_h(float* Hs, const float* bias,
                                        int mw, int nw, int g, int t,
                                        float d1[2][8][4]) {
    #pragma unroll
    for (int mt = 0; mt < 2; mt++) {
        int r = mw * 32 + mt * 16 + g;
        #pragma unroll
        for (int nt = 0; nt < 8; nt++) {
            int c = nw * 64 + nt * 8 + 2 * t;
            float b0 = bias[c], b1 = bias[c + 1];
            Hs[r * HS_STRIDE + c]           = tf32f(fmaxf(d1[mt][nt][0] + b0, 0.f));
            Hs[r * HS_STRIDE + c + 1]       = tf32f(fmaxf(d1[mt][nt][1] + b1, 0.f));
            Hs[(r + 8) * HS_STRIDE + c]     = tf32f(fmaxf(d1[mt][nt][2] + b0, 0.f));
            Hs[(r + 8) * HS_STRIDE + c + 1] = tf32f(fmaxf(d1[mt][nt][3] + b1, 0.f));
        }
    }
}

__device__ __forceinline__ void gemm2_chunk_mma(const float* Hs, const float* Bs,
                                                int c, int mw, int nw, int g, int t,
                                                float d2[2][4][4]) {
    #pragma unroll
    for (int ks = 0; ks < 4; ks++) {
        int kk = c * 32 + ks * 8;     // column in Hs
        int k = ks * 8;               // column in Bs chunk
        uint32_t a[2][4];
        #pragma unroll
        for (int mt = 0; mt < 2; mt++) {
            int r = mw * 32 + mt * 16;
            a[mt][0] = __float_as_uint(Hs[(r + g) * HS_STRIDE + kk + t]);
            a[mt][1] = __float_as_uint(Hs[(r + g + 8) * HS_STRIDE + kk + t]);
            a[mt][2] = __float_as_uint(Hs[(r + g) * HS_STRIDE + kk + t + 4]);
            a[mt][3] = __float_as_uint(Hs[(r + g + 8) * HS_STRIDE + kk + t + 4]);
        }
        #pragma unroll
        for (int nt = 0; nt < 4; nt++) {
            int n = nw * 32 + nt * 8;
            uint32_t b0 = __float_as_uint(Bs[(n + g) * BS_STRIDE + k + t]);
            uint32_t b1 = __float_as_uint(Bs[(n + g) * BS_STRIDE + k + t + 4]);
            mma8(d2[0][nt], a[0], b0, b1);
            mma8(d2[1][nt], a[1], b0, b1);
        }
    }
}

// ---------------- edge kernel ------------------------------------------------
__global__ __launch_bounds__(512, 1) void edge_mma_kernel(
    const float* __restrict__ node_in, const float* __restrict__ edge_in,
    const int* __restrict__ src, const int* __restrict__ dst,
    const float* __restrict__ W1T, const float* __restrict__ W2T,
    const float* __restrict__ b2, const float* __restrict__ qb,
    float* __restrict__ edge_out, float* __restrict__ agg) {
    extern __shared__ float sm[];
    float* Hs = sm + HS_OFF;
    float* As = sm + AS_OFF;
    float* Bs = sm + BS_OFF;
    float* qb_s = sm + QB_OFF;
    float* b2_s = sm + B2_OFF;
    int* ss = (int*)(sm + SS_OFF);
    int* sd = (int*)(sm + SD_OFF);

    const int tid = threadIdx.x;
    const int e0 = blockIdx.x * 128;
    if (tid < 256) qb_s[tid] = qb[tid];
    if (tid < 128) {
        b2_s[tid] = b2[tid];
        ss[tid] = src[e0 + tid];
        sd[tid] = dst[e0 + tid];
    }
    __syncthreads();

    const int w = tid >> 5, lane = tid & 31;
    const int mw = w >> 2, nw = w & 3;
    const int g = lane >> 2, t = lane & 3;

    // ---- GEMM1: [128,384] @ [384,256] ----
    float d1[2][8][4];
    #pragma unroll
    for (int i = 0; i < 2; i++)
        #pragma unroll
        for (int j = 0; j < 8; j++)
            #pragma unroll
            for (int q = 0; q < 4; q++) d1[i][j][q] = 0.f;

    const int sm_m = tid >> 2, sm_q = tid & 3;     // A staging: 128 rows x 4 quads
    const int sb_n = tid >> 1, sb_h = tid & 1;     // B staging: 256 rows x 2 halves

    #pragma unroll 1
    for (int c = 0; c < 12; c++) {
        __syncthreads();
        {   // stage A chunk (gathered, tf32-converted)
            int k = c * 32 + sm_q * 8;
            const float* sp;
            if (k < 128)      sp = node_in + (size_t)ss[sm_m] * DDIM + k;
            else if (k < 256) sp = node_in + (size_t)sd[sm_m] * DDIM + (k - 128);
            else              sp = edge_in + (size_t)(e0 + sm_m) * DDIM + (k - 256);
            float4 v0 = ((const float4*)sp)[0];
            float4 v1 = ((const float4*)sp)[1];
            float* dp = As + sm_m * AS_STRIDE + sm_q * 8;
            dp[0] = tf32f(v0.x); dp[1] = tf32f(v0.y); dp[2] = tf32f(v0.z); dp[3] = tf32f(v0.w);
            dp[4] = tf32f(v1.x); dp[5] = tf32f(v1.y); dp[6] = tf32f(v1.z); dp[7] = tf32f(v1.w);
        }
        {   // stage B chunk (already tf32)
            const float4* sp = (const float4*)(W1T + (size_t)sb_n * 384 + c * 32 + sb_h * 16);
            float4* dp = (float4*)(Bs + sb_n * BS_STRIDE + sb_h * 16);
            dp[0] = sp[0]; dp[1] = sp[1]; dp[2] = sp[2]; dp[3] = sp[3];
        }
        __syncthreads();
        gemm1_chunk_mma(As, Bs, mw, nw, g, t, d1);
    }

    write_h(Hs, qb_s, mw, nw, g, t, d1);

    // ---- GEMM2: [128,256] @ [256,128] ----
    float d2[2][4][4];
    #pragma unroll
    for (int i = 0; i < 2; i++)
        #pragma unroll
        for (int j = 0; j < 4; j++)
            #pragma unroll
            for (int q = 0; q < 4; q++) d2[i][j][q] = 0.f;

    const int s2_n = tid >> 2, s2_q = tid & 3;     // B2 staging: 128 rows x 4 quads

    #pragma unroll 1
    for (int c = 0; c < 8; c++) {
        __syncthreads();
        {
            const float4* sp = (const float4*)(W2T + (size_t)s2_n * 256 + c * 32 + s2_q * 8);
            float4* dp = (float4*)(Bs + s2_n * BS_STRIDE + s2_q * 8);
            dp[0] = sp[0]; dp[1] = sp[1];
        }
        __syncthreads();
        gemm2_chunk_mma(Hs, Bs, c, mw, nw, g, t, d2);
    }

    // ---- epilogue: store + atomic scatter ----
    #pragma unroll
    for (int mt = 0; mt < 2; mt++) {
        int r0 = mw * 32 + mt * 16 + g;
        #pragma unroll
        for (int half = 0; half < 2; half++) {
            int r = r0 + half * 8;
            int e = e0 + r;
            int s = ss[r], d = sd[r];
            #pragma unroll
            for (int nt = 0; nt < 4; nt++) {
                int c = nw * 32 + nt * 8 + 2 * t;
                float v0 = d2[mt][nt][half * 2 + 0] + b2_s[c];
                float v1 = d2[mt][nt][half * 2 + 1] + b2_s[c + 1];
                float* eo = edge_out + (size_t)e * DDIM + c;
                eo[0] = v0; eo[1] = v1;
                red2(agg + (size_t)s * DDIM + c, v0, v1);
                red2(agg + (size_t)d * DDIM + c, v0, v1);
            }
        }
    }
}

// ---------------- node kernel ------------------------------------------------
__global__ __launch_bounds__(512, 1) void node_mma_kernel(
    const float* __restrict__ node_in, const float* __restrict__ agg,
    const float* __restrict__ W1T, const float* __restrict__ W2T,
    const float* __restrict__ b1, const float* __restrict__ b2,
    float* __restrict__ node_out) {
    extern __shared__ float sm[];
    float* Hs = sm + HS_OFF;
    float* As = sm + AS_OFF;
    float* Bs = sm + BS_OFF;
    float* b1_s = sm + QB_OFF;
    float* b2_s = sm + B2_OFF;

    const int tid = threadIdx.x;
    const int n0 = blockIdx.x * 128;
    if (tid < 256) b1_s[tid] = b1[tid];
    if (tid < 128) b2_s[tid] = b2[tid];
    __syncthreads();

    const int w = tid >> 5, lane = tid & 31;
    const int mw = w >> 2, nw = w & 3;
    const int g = lane >> 2, t = lane & 3;

    float d1[2][8][4];
    #pragma unroll
    for (int i = 0; i < 2; i++)
        #pragma unroll
        for (int j = 0; j < 8; j++)
            #pragma unroll
            for (int q = 0; q < 4; q++) d1[i][j][q] = 0.f;

    const int sm_m = tid >> 2, sm_q = tid & 3;
    const int sb_n = tid >> 1, sb_h = tid & 1;
    int gm = n0 + sm_m; if (gm >= NN) gm = 0;

    // ---- GEMM1: [128, 256] @ [256, 256] ----
    #pragma unroll 1
    for (int c = 0; c < 8; c++) {
        __syncthreads();
        {
            int k = c * 32 + sm_q * 8;
            const float* sp = (k < 128) ? node_in + (size_t)gm * DDIM + k
                                        : agg + (size_t)gm * DDIM + (k - 128);
            float4 v0 = ((const float4*)sp)[0];
            float4 v1 = ((const float4*)sp)[1];
            float* dp = As + sm_m * AS_STRIDE + sm_q * 8;
            dp[0] = tf32f(v0.x); dp[1] = tf32f(v0.y); dp[2] = tf32f(v0.z); dp[3] = tf32f(v0.w);
            dp[4] = tf32f(v1.x); dp[5] = tf32f(v1.y); dp[6] = tf32f(v1.z); dp[7] = tf32f(v1.w);
        }
        {
            const float4* sp = (const float4*)(W1T + (size_t)sb_n * 256 + c * 32 + sb_h * 16);
            float4* dp = (float4*)(Bs + sb_n * BS_STRIDE + sb_h * 16);
            dp[0] = sp[0]; dp[1] = sp[1]; dp[2] = sp[2]; dp[3] = sp[3];
        }
        __syncthreads();
        gemm1_chunk_mma(As, Bs, mw, nw, g, t, d1);
    }

    write_h(Hs, b1_s, mw, nw, g, t, d1);

    // ---- GEMM2: [128,256] @ [256,128] ----
    float d2[2][4][4];
    #pragma unroll
    for (int i = 0; i < 2; i++)
        #pragma unroll
        for (int j = 0; j < 4; j++)
            #pragma unroll
            for (int q = 0; q < 4; q++) d2[i][j][q] = 0.f;

    const int s2_n = tid >> 2, s2_q = tid & 3;

    #pragma unroll 1
    for (int c = 0; c < 8; c++) {
        __syncthreads();
        {
            const float4* sp = (const float4*)(W2T + (size_t)s2_n * 256 + c * 32 + s2_q * 8);
            float4* dp = (float4*)(Bs + s2_n * BS_STRIDE + s2_q * 8);
            dp[0] = sp[0]; dp[1] = sp[1];
        }
        __syncthreads();
        gemm2_chunk_mma(Hs, Bs, c, mw, nw, g, t, d2);
    }

    // ---- epilogue: store (guarded for tail tile) ----
    #pragma unroll
    for (int mt = 0; mt < 2; mt++) {
        int r0 = mw * 32 + mt * 16 + g;
        #pragma unroll
        for (int half = 0; half < 2; half++) {
            int r = n0 + r0 + half * 8;
            if (r < NN) {
                #pragma unroll
                for (int nt = 0; nt < 4; nt++) {
                    int c = nw * 32 + nt * 8 + 2 * t;
                    float* no = node_out + (size_t)r * DDIM + c;
                    no[0] = d2[mt][nt][half * 2 + 0] + b2_s[c];
                    no[1] = d2[mt][nt][half * 2 + 1] + b2_s[c + 1];
                }
            }
        }
    }
}

// ---------------- launch ----------------------------------------------------
extern "C" void kernel_launch(void* const* d_in, const int* in_sizes, int n_in,
                              void* d_out, int out_size) {
    const float* node_emb = (const float*)d_in[0];
    const float* rel_emb  = (const float*)d_in[1];
    const float* q_emb    = (const float*)d_in[2];
    const int*   eidx     = (const int*)d_in[3];
    // d_in[4] = edge_type, unused (matches reference)
    const float* qW  = (const float*)d_in[5];
    const float* qb  = (const float*)d_in[6];
    const float* eW1 = (const float*)d_in[7];
    const float* eb1 = (const float*)d_in[8];
    const float* eW2 = (const float*)d_in[9];
    const float* eb2 = (const float*)d_in[10];
    const float* nW1 = (const float*)d_in[11];
    const float* nb1 = (const float*)d_in[12];
    const float* nW2 = (const float*)d_in[13];
    const float* nb2 = (const float*)d_in[14];
    const float* esW = (const float*)d_in[15];
    const float* esb = (const float*)d_in[16];
    const float* nsW = (const float*)d_in[17];
    const float* nsb = (const float*)d_in[18];
    const int* src = eidx;
    const int* dst = eidx + EE;

    float *nodeA, *nodeB, *edgeA, *edgeB, *agg, *qv, *qbias;
    float *eW1T, *eW2T, *nW1T, *nW2T;
    cudaGetSymbolAddress((void**)&nodeA, g_nodeA);
    cudaGetSymbolAddress((void**)&nodeB, g_nodeB);
    cudaGetSymbolAddress((void**)&edgeA, g_edgeA);
    cudaGetSymbolAddress((void**)&edgeB, g_edgeB);
    cudaGetSymbolAddress((void**)&agg, g_agg);
    cudaGetSymbolAddress((void**)&qv, g_q);
    cudaGetSymbolAddress((void**)&qbias, g_qbias);
    cudaGetSymbolAddress((void**)&eW1T, g_eW1T);
    cudaGetSymbolAddress((void**)&eW2T, g_eW2T);
    cudaGetSymbolAddress((void**)&nW1T, g_nW1T);
    cudaGetSymbolAddress((void**)&nW2T, g_nW2T);

    cudaFuncSetAttribute(edge_mma_kernel, cudaFuncAttributeMaxDynamicSharedMemorySize, SMEM_BYTES);
    cudaFuncSetAttribute(node_mma_kernel, cudaFuncAttributeMaxDynamicSharedMemorySize, SMEM_BYTES);

    q_proj_kernel<<<1, 128>>>(q_emb, qW, qb, qv);

    const float* nin = node_emb;
    const float* ein = rel_emb;
    float* nout = nodeA; float* nalt = nodeB;
    float* eout = edgeA; float* ealt = edgeB;

    for (int l = 0; l < LLAY; l++) {
        int n4 = NN * DDIM / 4;
        zero_kernel<<<(n4 + 255) / 256, 256>>>((float4*)agg, n4);
        qbias_kernel<<<1, 256>>>(qv, eW1 + (size_t)l * 512 * HHID, eb1 + (size_t)l * HHID, qbias);
        transpose_tf32_kernel<<<(256 * 384 + 255) / 256, 256>>>(
            eW1 + (size_t)l * 512 * HHID, eW1T, 384, 256);
        transpose_tf32_kernel<<<(128 * 256 + 255) / 256, 256>>>(
            eW2 + (size_t)l * HHID * DDIM, eW2T, 256, 128);
        transpose_tf32_kernel<<<(256 * 256 + 255) / 256, 256>>>(
            nW1 + (size_t)l * 2 * DDIM * HHID, nW1T, 256, 256);
        transpose_tf32_kernel<<<(128 * 256 + 255) / 256, 256>>>(
            nW2 + (size_t)l * HHID * DDIM, nW2T, 256, 128);

        edge_mma_kernel<<<EE / 128, 512, SMEM_BYTES>>>(nin, ein, src, dst, eW1T, eW2T,
                                                       eb2 + (size_t)l * DDIM, qbias, eout, agg);
        node_mma_kernel<<<(NN + 127) / 128, 512, SMEM_BYTES>>>(nin, agg, nW1T, nW2T,
                                                               nb1 + (size_t)l * HHID,
                                                               nb2 + (size_t)l * DDIM, nout);
        nin = nout; ein = eout;
        float* tptr;
        tptr = nout; nout = nalt; nalt = tptr;
        tptr = eout; eout = ealt; ealt = tptr;
    }

    float* outp = (float*)d_out;
    score_kernel<<<(NN + 7) / 8, 256>>>(nin, nsW, nsb, outp, NN);
    score_kernel<<<(EE + 7) / 8, 256>>>(ein, esW, esb, outp + NN, EE);
}